// round 3
// baseline (speedup 1.0000x reference)
#include <cuda_runtime.h>

// Problem constants
#define M_TOK 32768
#define K_IN  768
#define N_OUT 3072
#define NS    134          // number of singular values
// T has 134 * 144 (I,O pairs) blocks of 128 (a*16+b)
#define T_BLOCKS (NS * 144)

// Device scratch (allocation-free per harness rules)
__device__ float g_T[(size_t)T_BLOCKS * 128];   // ~9.9 MB
__device__ float g_W[(size_t)K_IN * N_OUT];     // ~9.4 MB

// ---------------------------------------------------------------------------
// Kernel 1: T[s,I,O,a,b] = sum_S W2[s,I,O,S] * W3[S,a,b]
// grid = 19296 blocks (one per (s,I,O)), 128 threads (one per (a,b))
// W3 total is 68.6 KB -> fully L2-resident after first touch.
// ---------------------------------------------------------------------------
__global__ void compute_T_kernel(const float* __restrict__ W2,
                                 const float* __restrict__ W3) {
    int blk = blockIdx.x;              // s*144 + (I*12+O)
    int t   = threadIdx.x;             // a*16 + b
    __shared__ float sw2[NS];
    const float* w2p = W2 + (size_t)blk * NS;
    for (int j = t; j < NS; j += 128) sw2[j] = w2p[j];
    __syncthreads();
    float acc = 0.f;
    for (int S = 0; S < NS; S++)
        acc += sw2[S] * __ldg(&W3[S * 128 + t]);
    g_T[(size_t)blk * 128 + t] = acc;
}

// ---------------------------------------------------------------------------
// Kernel 2: W[r,c] with r=(i*12+I)*8+a, c=(o*12+O)*16+b
//           W = sum_s W1[i,o,s] * T[s,I,O,a,b]
// grid = 144 blocks (one per (I,O)), 256 threads (one per (o,b)).
// Each thread accumulates the 8x8 (i,a) tile for its (o,b).
// ---------------------------------------------------------------------------
__global__ void compute_W_kernel(const float* __restrict__ W1) {
    int IO = blockIdx.x;               // I*12 + O
    int I = IO / 12, O = IO % 12;
    int t = threadIdx.x;               // 0..255
    int o = t >> 4, b = t & 15;

    __shared__ float sW1[32][128];     // [ss][(i*16+o)]
    __shared__ float sT[32][128];      // [ss][(a*16+b)]

    float acc[64];
#pragma unroll
    for (int i = 0; i < 64; i++) acc[i] = 0.f;

    for (int s0 = 0; s0 < NS; s0 += 32) {
        int ns = min(32, NS - s0);
        for (int j = t; j < ns * 128; j += 256) {
            int ss = j >> 7, io = j & 127;
            sW1[ss][io] = W1[io * NS + s0 + ss];   // W1[(i*16+o)*134 + s]
        }
        for (int j = t; j < ns * 128; j += 256) {
            int ss = j >> 7, ab = j & 127;
            sT[ss][ab] = g_T[((size_t)(s0 + ss) * 144 + IO) * 128 + ab];
        }
        __syncthreads();
        for (int ss = 0; ss < ns; ss++) {
            float w1v[8], tv[8];
#pragma unroll
            for (int i = 0; i < 8; i++) w1v[i] = sW1[ss][i * 16 + o];  // broadcast in half-warp
#pragma unroll
            for (int a = 0; a < 8; a++) tv[a] = sT[ss][a * 16 + b];
#pragma unroll
            for (int i = 0; i < 8; i++)
#pragma unroll
                for (int a = 0; a < 8; a++)
                    acc[i * 8 + a] += w1v[i] * tv[a];
        }
        __syncthreads();
    }

    int cbase = (o * 12 + O) * 16 + b;
#pragma unroll
    for (int i = 0; i < 8; i++)
#pragma unroll
        for (int a = 0; a < 8; a++) {
            int r = (i * 12 + I) * 8 + a;
            g_W[(size_t)r * N_OUT + cbase] = acc[i * 8 + a];
        }
}

// ---------------------------------------------------------------------------
// Kernel 3: C = x @ W + bias  (M=32768, K=768, N=3072, fp32)
// 128x128 block tile, BK=16, 256 threads, 8x8 register micro-tile.
// ---------------------------------------------------------------------------
#define BM 128
#define BN 128
#define BK 16

__global__ __launch_bounds__(256, 2)
void gemm_kernel(const float* __restrict__ A,
                 const float* __restrict__ bias,
                 float* __restrict__ C) {
    __shared__ float sA[BK][BM + 4];   // transposed A tile, +4 pad kills store conflicts
    __shared__ float sB[BK][BN];

    int t  = threadIdx.x;
    int tx = t & 15;                   // column group (8 cols)
    int ty = t >> 4;                   // row group (8 rows)
    int m0 = blockIdx.y * BM;
    int n0 = blockIdx.x * BN;

    float acc[8][8];
#pragma unroll
    for (int i = 0; i < 8; i++)
#pragma unroll
        for (int j = 0; j < 8; j++) acc[i][j] = 0.f;

    for (int k0 = 0; k0 < K_IN; k0 += BK) {
        // Load A tile: 128 rows x 16 k -> 512 float4, 2 per thread. Transpose.
#pragma unroll
        for (int l = 0; l < 2; l++) {
            int id  = t + l * 256;
            int row = id >> 2;
            int kq  = (id & 3) * 4;
            float4 v = *reinterpret_cast<const float4*>(
                &A[(size_t)(m0 + row) * K_IN + k0 + kq]);
            sA[kq + 0][row] = v.x;
            sA[kq + 1][row] = v.y;
            sA[kq + 2][row] = v.z;
            sA[kq + 3][row] = v.w;
        }
        // Load B tile: 16 k x 128 cols -> 512 float4, coalesced, no transpose.
#pragma unroll
        for (int l = 0; l < 2; l++) {
            int id = t + l * 256;
            int kk = id >> 5;
            int cq = (id & 31) * 4;
            float4 v = *reinterpret_cast<const float4*>(
                &g_W[(size_t)(k0 + kk) * N_OUT + n0 + cq]);
            *reinterpret_cast<float4*>(&sB[kk][cq]) = v;
        }
        __syncthreads();

#pragma unroll
        for (int kk = 0; kk < BK; kk++) {
            float4 a0 = *reinterpret_cast<float4*>(&sA[kk][ty * 8]);
            float4 a1 = *reinterpret_cast<float4*>(&sA[kk][ty * 8 + 4]);
            float4 b0 = *reinterpret_cast<float4*>(&sB[kk][tx * 8]);
            float4 b1 = *reinterpret_cast<float4*>(&sB[kk][tx * 8 + 4]);
            float af[8] = {a0.x, a0.y, a0.z, a0.w, a1.x, a1.y, a1.z, a1.w};
            float bf[8] = {b0.x, b0.y, b0.z, b0.w, b1.x, b1.y, b1.z, b1.w};
#pragma unroll
            for (int i = 0; i < 8; i++)
#pragma unroll
                for (int j = 0; j < 8; j++)
                    acc[i][j] += af[i] * bf[j];
        }
        __syncthreads();
    }

    // Epilogue: add bias, vectorized stores.
    float bn[8];
#pragma unroll
    for (int j = 0; j < 8; j++) bn[j] = __ldg(&bias[n0 + tx * 8 + j]);

#pragma unroll
    for (int i = 0; i < 8; i++) {
        int m = m0 + ty * 8 + i;
        float4 o0, o1;
        o0.x = acc[i][0] + bn[0];
        o0.y = acc[i][1] + bn[1];
        o0.z = acc[i][2] + bn[2];
        o0.w = acc[i][3] + bn[3];
        o1.x = acc[i][4] + bn[4];
        o1.y = acc[i][5] + bn[5];
        o1.z = acc[i][6] + bn[6];
        o1.w = acc[i][7] + bn[7];
        float* cp = &C[(size_t)m * N_OUT + n0 + tx * 8];
        *reinterpret_cast<float4*>(cp)     = o0;
        *reinterpret_cast<float4*>(cp + 4) = o1;
    }
}

// ---------------------------------------------------------------------------
// Launch. Inputs (metadata order): x, W_1, W_2, W_3, b. Output: fp32 (32768,3072)
// ---------------------------------------------------------------------------
extern "C" void kernel_launch(void* const* d_in, const int* in_sizes, int n_in,
                              void* d_out, int out_size) {
    const float* x  = (const float*)d_in[0];
    const float* W1 = (const float*)d_in[1];
    const float* W2 = (const float*)d_in[2];
    const float* W3 = (const float*)d_in[3];
    const float* b  = (const float*)d_in[4];
    float* out = (float*)d_out;

    compute_T_kernel<<<T_BLOCKS, 128>>>(W2, W3);
    compute_W_kernel<<<144, 256>>>(W1);
    gemm_kernel<<<dim3(N_OUT / BN, M_TOK / BM), 256>>>(x, b, out);
}

// round 8
// speedup vs baseline: 1.7454x; 1.7454x over previous
#include <cuda_runtime.h>
#include <cuda_bf16.h>
#include <cstdint>

// ============================================================================
// Problem constants
// ============================================================================
#define M_TOK 32768
#define K_IN  768
#define N_OUT 3072
#define NS    134
#define T_BLOCKS (NS * 144)

// GEMM tiling
#define BM 128
#define BN 256
#define BK 32
#define NKB (K_IN / BK)        // 24 k-blocks per segment
#define NSEG 3                 // hi*hi, lo*hi, hi*lo
#define NIT (NSEG * NKB)       // 72
#define M_TILES (M_TOK / BM)   // 256
#define N_TILES (N_OUT / BN)   // 12

#define A_STAGE_BYTES (BM * BK * 2)      // 8192
#define B_STAGE_BYTES (BN * BK * 2)      // 16384
#define STAGE_BYTES (A_STAGE_BYTES + B_STAGE_BYTES)  // 24576
#define NSTAGES 3
#define SMEM_TOTAL (NSTAGES * STAGE_BYTES)           // 73728

// ============================================================================
// Device scratch (allocation-free)
// ============================================================================
__device__ float g_T[(size_t)T_BLOCKS * 128];          // 9.9 MB
__device__ float g_Wt[(size_t)N_OUT * K_IN];           // 9.4 MB, W transposed [n][k]
__device__ __nv_bfloat16 g_Ahi[(size_t)M_TOK * K_IN];  // 48 MB
__device__ __nv_bfloat16 g_Alo[(size_t)M_TOK * K_IN];  // 48 MB
__device__ __nv_bfloat16 g_Bhi[(size_t)N_OUT * K_IN];  // 4.5 MB
__device__ __nv_bfloat16 g_Blo[(size_t)N_OUT * K_IN];  // 4.5 MB

// ============================================================================
// PTX helpers (all plain sm_80+/sm_90 PTX — no 'a'-suffix features)
// ============================================================================
__device__ __forceinline__ uint32_t smem_u32(const void* p) {
    uint32_t a;
    asm("{ .reg .u64 t; cvta.to.shared.u64 t, %1; cvt.u32.u64 %0, t; }" : "=r"(a) : "l"(p));
    return a;
}

__device__ __forceinline__ void cp16(uint32_t dst, const void* src) {
    asm volatile("cp.async.cg.shared.global [%0], [%1], 16;" :: "r"(dst), "l"(src));
}
#define CP_COMMIT() asm volatile("cp.async.commit_group;" ::: "memory")
#define CP_WAIT2()  asm volatile("cp.async.wait_group 2;" ::: "memory")

#define LDMATRIX_X4(r0, r1, r2, r3, addr) \
    asm volatile("ldmatrix.sync.aligned.m8n8.x4.shared.b16 {%0,%1,%2,%3}, [%4];" \
                 : "=r"(r0), "=r"(r1), "=r"(r2), "=r"(r3) : "r"(addr))

#define MMA_BF16(d, a0, a1, a2, a3, b0, b1) \
    asm volatile("mma.sync.aligned.m16n8k16.row.col.f32.bf16.bf16.f32 " \
                 "{%0,%1,%2,%3}, {%4,%5,%6,%7}, {%8,%9}, {%0,%1,%2,%3};" \
                 : "+f"((d)[0]), "+f"((d)[1]), "+f"((d)[2]), "+f"((d)[3]) \
                 : "r"(a0), "r"(a1), "r"(a2), "r"(a3), "r"(b0), "r"(b1))

// Swizzle: row r (64B = 4 x 16B chunks), chunk c -> c ^ ((r>>1)&3).
__device__ __forceinline__ uint32_t swz(int r, int c) {
    return (uint32_t)(r * 64 + ((c ^ ((r >> 1) & 3)) << 4));
}

// ============================================================================
// Kernel 1: T[s,I,O,a,b] = sum_S W2[s,I,O,S] * W3[S,a,b]
// ============================================================================
__global__ void compute_T_kernel(const float* __restrict__ W2,
                                 const float* __restrict__ W3) {
    int blk = blockIdx.x;
    int t   = threadIdx.x;
    __shared__ float sw2[NS];
    const float* w2p = W2 + (size_t)blk * NS;
    for (int j = t; j < NS; j += 128) sw2[j] = w2p[j];
    __syncthreads();
    float acc = 0.f;
    for (int S = 0; S < NS; S++)
        acc += sw2[S] * __ldg(&W3[S * 128 + t]);
    g_T[(size_t)blk * 128 + t] = acc;
}

// ============================================================================
// Kernel 2: W transposed — g_Wt[c*768 + r] = sum_s W1[i,o,s] * T[s,I,O,a,b]
//           r=(i*12+I)*8+a, c=(o*12+O)*16+b
// ============================================================================
__global__ void compute_Wt_kernel(const float* __restrict__ W1) {
    int IO = blockIdx.x;
    int I = IO / 12, O = IO % 12;
    int t = threadIdx.x;
    int o = t >> 4, b = t & 15;

    __shared__ float sW1[32][128];
    __shared__ float sT[32][128];

    float acc[64];
#pragma unroll
    for (int i = 0; i < 64; i++) acc[i] = 0.f;

    for (int s0 = 0; s0 < NS; s0 += 32) {
        int ns = min(32, NS - s0);
        for (int j = t; j < ns * 128; j += 256) {
            int ss = j >> 7, io = j & 127;
            sW1[ss][io] = W1[io * NS + s0 + ss];
        }
        for (int j = t; j < ns * 128; j += 256) {
            int ss = j >> 7, ab = j & 127;
            sT[ss][ab] = g_T[((size_t)(s0 + ss) * 144 + IO) * 128 + ab];
        }
        __syncthreads();
        for (int ss = 0; ss < ns; ss++) {
            float w1v[8], tv[8];
#pragma unroll
            for (int i = 0; i < 8; i++) w1v[i] = sW1[ss][i * 16 + o];
#pragma unroll
            for (int a = 0; a < 8; a++) tv[a] = sT[ss][a * 16 + b];
#pragma unroll
            for (int i = 0; i < 8; i++)
#pragma unroll
                for (int a = 0; a < 8; a++)
                    acc[i * 8 + a] += w1v[i] * tv[a];
        }
        __syncthreads();
    }

    int c = (o * 12 + O) * 16 + b;
#pragma unroll
    for (int i = 0; i < 8; i++)
#pragma unroll
        for (int a = 0; a < 8; a++) {
            int r = (i * 12 + I) * 8 + a;
            g_Wt[(size_t)c * K_IN + r] = acc[i * 8 + a];
        }
}

// ============================================================================
// Kernel 3: x -> hi/lo bf16, row-major [M][K]
// ============================================================================
__global__ void convert_x_kernel(const float* __restrict__ x) {
    size_t gt = (size_t)blockIdx.x * blockDim.x + threadIdx.x;  // 0 .. M*96-1
    const float* xp = x + gt * 8;
    float4 v0 = *reinterpret_cast<const float4*>(xp);
    float4 v1 = *reinterpret_cast<const float4*>(xp + 4);
    float f[8] = {v0.x, v0.y, v0.z, v0.w, v1.x, v1.y, v1.z, v1.w};
    uint32_t hw[4], lw[4];
#pragma unroll
    for (int j = 0; j < 4; j++) {
        __nv_bfloat16 h0 = __float2bfloat16(f[2*j]);
        __nv_bfloat16 h1 = __float2bfloat16(f[2*j+1]);
        __nv_bfloat16 l0 = __float2bfloat16(f[2*j]   - __bfloat162float(h0));
        __nv_bfloat16 l1 = __float2bfloat16(f[2*j+1] - __bfloat162float(h1));
        hw[j] = (uint32_t)__bfloat16_as_ushort(h0) | ((uint32_t)__bfloat16_as_ushort(h1) << 16);
        lw[j] = (uint32_t)__bfloat16_as_ushort(l0) | ((uint32_t)__bfloat16_as_ushort(l1) << 16);
    }
    *reinterpret_cast<uint4*>(&g_Ahi[gt * 8]) = make_uint4(hw[0], hw[1], hw[2], hw[3]);
    *reinterpret_cast<uint4*>(&g_Alo[gt * 8]) = make_uint4(lw[0], lw[1], lw[2], lw[3]);
}

// ============================================================================
// Kernel 4: g_Wt (fp32 [n][k]) -> hi/lo bf16 [n][k]
// ============================================================================
__global__ void convert_W_kernel() {
    size_t gt = (size_t)blockIdx.x * blockDim.x + threadIdx.x;  // 0 .. N*96-1
    const float* wp = g_Wt + gt * 8;
    float4 v0 = *reinterpret_cast<const float4*>(wp);
    float4 v1 = *reinterpret_cast<const float4*>(wp + 4);
    float f[8] = {v0.x, v0.y, v0.z, v0.w, v1.x, v1.y, v1.z, v1.w};
    uint32_t hw[4], lw[4];
#pragma unroll
    for (int j = 0; j < 4; j++) {
        __nv_bfloat16 h0 = __float2bfloat16(f[2*j]);
        __nv_bfloat16 h1 = __float2bfloat16(f[2*j+1]);
        __nv_bfloat16 l0 = __float2bfloat16(f[2*j]   - __bfloat162float(h0));
        __nv_bfloat16 l1 = __float2bfloat16(f[2*j+1] - __bfloat162float(h1));
        hw[j] = (uint32_t)__bfloat16_as_ushort(h0) | ((uint32_t)__bfloat16_as_ushort(h1) << 16);
        lw[j] = (uint32_t)__bfloat16_as_ushort(l0) | ((uint32_t)__bfloat16_as_ushort(l1) << 16);
    }
    *reinterpret_cast<uint4*>(&g_Bhi[gt * 8]) = make_uint4(hw[0], hw[1], hw[2], hw[3]);
    *reinterpret_cast<uint4*>(&g_Blo[gt * 8]) = make_uint4(lw[0], lw[1], lw[2], lw[3]);
}

// ============================================================================
// Kernel 5: GEMM via mma.sync bf16.  C = sum over 3 segments (x_s @ W_s^T) + b
// 512 threads = 16 warps (4 m x 4 n), warp tile 32x64, BK=32, 3-stage cp.async.
// ============================================================================
__global__ __launch_bounds__(512, 1)
void gemm_mma_kernel(const float* __restrict__ bias, float* __restrict__ C) {
    extern __shared__ unsigned char smem[];
    const uint32_t sbase = smem_u32(smem);

    const int tid  = threadIdx.x;
    const int wid  = tid >> 5;
    const int lane = tid & 31;
    const int m0 = blockIdx.y * BM;
    const int n0 = blockIdx.x * BN;
    const int warp_m = (wid & 3) * 32;   // 0,32,64,96
    const int warp_n = (wid >> 2) * 64;  // 0,64,128,192

    // cp.async load assignments
    const int a_row = tid >> 2;          // 0..127
    const int a_c   = tid & 3;
    const uint32_t a_dst_off = swz(a_row, a_c);

    float acc[2][8][4];
#pragma unroll
    for (int i = 0; i < 2; i++)
#pragma unroll
        for (int j = 0; j < 8; j++)
#pragma unroll
            for (int q = 0; q < 4; q++) acc[i][j][q] = 0.f;

    // ---- stage loader ----
    auto load_stage = [&](int stage, int it) {
        int seg = it / NKB;
        int k0  = (it - seg * NKB) * BK;
        const __nv_bfloat16* Aseg = (seg == 1) ? g_Alo : g_Ahi;
        const __nv_bfloat16* Bseg = (seg == 2) ? g_Blo : g_Bhi;
        uint32_t sA = sbase + stage * STAGE_BYTES;
        uint32_t sB = sA + A_STAGE_BYTES;
        // A: 128 rows x 4 chunks = 512 -> 1 per thread
        cp16(sA + a_dst_off, Aseg + (size_t)(m0 + a_row) * K_IN + k0 + a_c * 8);
        // B: 256 rows x 4 chunks = 1024 -> 2 per thread
#pragma unroll
        for (int j = 0; j < 2; j++) {
            int id  = tid + j * 512;
            int row = id >> 2;
            int c   = id & 3;
            cp16(sB + swz(row, c), Bseg + (size_t)(n0 + row) * K_IN + k0 + c * 8);
        }
    };

    // Prologue: stages 0 and 1
    load_stage(0, 0); CP_COMMIT();
    load_stage(1, 1); CP_COMMIT();

    for (int it = 0; it < NIT; it++) {
        if (it + 2 < NIT) load_stage((it + 2) % NSTAGES, it + 2);
        CP_COMMIT();
        CP_WAIT2();               // stage it%3 complete
        __syncthreads();

        uint32_t sA = sbase + (it % NSTAGES) * STAGE_BYTES;
        uint32_t sB = sA + A_STAGE_BYTES;

#pragma unroll
        for (int ks = 0; ks < 2; ks++) {
            // A fragments: 2 tiles of m16 x k16
            uint32_t aF[2][4];
#pragma unroll
            for (int mt = 0; mt < 2; mt++) {
                int r = warp_m + mt * 16 + (lane & 15);
                int c = ks * 2 + (lane >> 4);
                LDMATRIX_X4(aF[mt][0], aF[mt][1], aF[mt][2], aF[mt][3], sA + swz(r, c));
            }
            // B fragments: 4 tiles of n16 x k16 (each = 2 n8 tiles)
            uint32_t bF[4][4];
#pragma unroll
            for (int nt = 0; nt < 4; nt++) {
                int r = warp_n + nt * 16 + (lane & 15);
                int c = ks * 2 + (lane >> 4);
                LDMATRIX_X4(bF[nt][0], bF[nt][1], bF[nt][2], bF[nt][3], sB + swz(r, c));
            }
#pragma unroll
            for (int mt = 0; mt < 2; mt++)
#pragma unroll
                for (int nt = 0; nt < 4; nt++)
#pragma unroll
                    for (int p = 0; p < 2; p++) {
                        MMA_BF16(acc[mt][nt * 2 + p],
                                 aF[mt][0], aF[mt][1], aF[mt][2], aF[mt][3],
                                 bF[nt][p], bF[nt][2 + p]);
                    }
        }
        __syncthreads();          // all reads done before next overwrite
    }

    // ---- Epilogue: bias + store ----
    const int g = lane >> 2, tig = lane & 3;
    float bv[8][2];
#pragma unroll
    for (int nn = 0; nn < 8; nn++) {
        int col = n0 + warp_n + nn * 8 + tig * 2;
        bv[nn][0] = __ldg(&bias[col]);
        bv[nn][1] = __ldg(&bias[col + 1]);
    }
#pragma unroll
    for (int mt = 0; mt < 2; mt++) {
        int r0 = m0 + warp_m + mt * 16 + g;
        int r1 = r0 + 8;
#pragma unroll
        for (int nn = 0; nn < 8; nn++) {
            int col = n0 + warp_n + nn * 8 + tig * 2;
            float2 v0 = make_float2(acc[mt][nn][0] + bv[nn][0], acc[mt][nn][1] + bv[nn][1]);
            float2 v1 = make_float2(acc[mt][nn][2] + bv[nn][0], acc[mt][nn][3] + bv[nn][1]);
            *reinterpret_cast<float2*>(&C[(size_t)r0 * N_OUT + col]) = v0;
            *reinterpret_cast<float2*>(&C[(size_t)r1 * N_OUT + col]) = v1;
        }
    }
}

// ============================================================================
// Launch. Inputs: x, W_1, W_2, W_3, b. Output fp32 (32768, 3072).
// ============================================================================
extern "C" void kernel_launch(void* const* d_in, const int* in_sizes, int n_in,
                              void* d_out, int out_size) {
    const float* x  = (const float*)d_in[0];
    const float* W1 = (const float*)d_in[1];
    const float* W2 = (const float*)d_in[2];
    const float* W3 = (const float*)d_in[3];
    const float* b  = (const float*)d_in[4];
    float* out = (float*)d_out;

    cudaFuncSetAttribute(gemm_mma_kernel,
                         cudaFuncAttributeMaxDynamicSharedMemorySize, SMEM_TOTAL);

    compute_T_kernel<<<T_BLOCKS, 128>>>(W2, W3);
    compute_Wt_kernel<<<144, 256>>>(W1);
    convert_x_kernel<<<(M_TOK * 96) / 256, 256>>>(x);
    convert_W_kernel<<<(N_OUT * 96) / 256, 256>>>();
    gemm_mma_kernel<<<dim3(N_TILES, M_TILES), 512, SMEM_TOTAL>>>(b, out);
}

// round 9
// speedup vs baseline: 1.9840x; 1.1367x over previous
#include <cuda_runtime.h>
#include <cuda_bf16.h>
#include <cstdint>

// ============================================================================
// Problem constants
// ============================================================================
#define M_TOK 32768
#define K_IN  768
#define N_OUT 3072
#define NS    134
#define T_BLOCKS (NS * 144)

// GEMM tiling
#define BM 128
#define BN 256
#define BK 64
#define NKB (K_IN / BK)        // 12 k-blocks per segment
#define NSEG 3                 // hi*hi, lo*hi, hi*lo
#define NIT (NSEG * NKB)       // 36
#define M_TILES (M_TOK / BM)   // 256
#define N_TILES (N_OUT / BN)   // 12

#define A_STAGE_BYTES (BM * BK * 2)      // 16384
#define B_STAGE_BYTES (BN * BK * 2)      // 32768
#define STAGE_BYTES (A_STAGE_BYTES + B_STAGE_BYTES)  // 49152
#define NSTAGES 3
#define SMEM_TOTAL (NSTAGES * STAGE_BYTES)           // 147456

// ============================================================================
// Device scratch (allocation-free)
// ============================================================================
__device__ float g_T[(size_t)T_BLOCKS * 128];          // 9.9 MB
__device__ float g_Wt[(size_t)N_OUT * K_IN];           // 9.4 MB, W transposed [n][k]
__device__ __nv_bfloat16 g_Ahi[(size_t)M_TOK * K_IN];  // 48 MB
__device__ __nv_bfloat16 g_Alo[(size_t)M_TOK * K_IN];  // 48 MB
__device__ __nv_bfloat16 g_Bhi[(size_t)N_OUT * K_IN];  // 4.5 MB
__device__ __nv_bfloat16 g_Blo[(size_t)N_OUT * K_IN];  // 4.5 MB

// ============================================================================
// PTX helpers (plain sm_80+ PTX only)
// ============================================================================
__device__ __forceinline__ uint32_t smem_u32(const void* p) {
    uint32_t a;
    asm("{ .reg .u64 t; cvta.to.shared.u64 t, %1; cvt.u32.u64 %0, t; }" : "=r"(a) : "l"(p));
    return a;
}

__device__ __forceinline__ void cp16(uint32_t dst, const void* src) {
    asm volatile("cp.async.cg.shared.global [%0], [%1], 16;" :: "r"(dst), "l"(src));
}
#define CP_COMMIT() asm volatile("cp.async.commit_group;" ::: "memory")
#define CP_WAIT1()  asm volatile("cp.async.wait_group 1;" ::: "memory")

#define LDMATRIX_X4(r0, r1, r2, r3, addr) \
    asm volatile("ldmatrix.sync.aligned.m8n8.x4.shared.b16 {%0,%1,%2,%3}, [%4];" \
                 : "=r"(r0), "=r"(r1), "=r"(r2), "=r"(r3) : "r"(addr))

#define MMA_BF16(d, a0, a1, a2, a3, b0, b1) \
    asm volatile("mma.sync.aligned.m16n8k16.row.col.f32.bf16.bf16.f32 " \
                 "{%0,%1,%2,%3}, {%4,%5,%6,%7}, {%8,%9}, {%0,%1,%2,%3};" \
                 : "+f"((d)[0]), "+f"((d)[1]), "+f"((d)[2]), "+f"((d)[3]) \
                 : "r"(a0), "r"(a1), "r"(a2), "r"(a3), "r"(b0), "r"(b1))

// 128B-row swizzle: row r, 16B chunk c (0..7) -> c ^ (r & 7).
// ldmatrix 8-row phases hit 8 distinct chunks -> conflict-free.
__device__ __forceinline__ uint32_t swz128(int r, int c) {
    return (uint32_t)(r * 128 + ((c ^ (r & 7)) << 4));
}

// ============================================================================
// Kernel 1: T[s,I,O,a,b] = sum_S W2[s,I,O,S] * W3[S,a,b]
// W3 (68.6 KB) cached in dynamic smem; 8 s-values per block -> L1 traffic /8.
// grid = ceil(134/8)*144 = 2448, block = 128
// ============================================================================
__global__ void compute_T_kernel(const float* __restrict__ W2,
                                 const float* __restrict__ W3) {
    extern __shared__ float sW3[];           // NS*128 floats
    __shared__ float sw2[8][NS];
    int blk = blockIdx.x;
    int sc  = blk / 144;
    int IO  = blk % 144;
    int t   = threadIdx.x;

    for (int j = t; j < NS * 128; j += 128) sW3[j] = W3[j];
    int s0  = sc * 8;
    int nsv = min(8, NS - s0);
    for (int j = t; j < nsv * NS; j += 128) {
        int ss = j / NS, k = j - ss * NS;
        sw2[ss][k] = W2[((size_t)(s0 + ss) * 144 + IO) * NS + k];
    }
    __syncthreads();

    for (int ss = 0; ss < nsv; ss++) {
        float acc = 0.f;
#pragma unroll 2
        for (int S = 0; S < NS; S++)
            acc += sw2[ss][S] * sW3[S * 128 + t];
        g_T[((size_t)(s0 + ss) * 144 + IO) * 128 + t] = acc;
    }
}

// ============================================================================
// Kernel 2: W transposed — g_Wt[c*768 + r] = sum_s W1[i,o,s] * T[s,I,O,a,b]
//           r=(i*12+I)*8+a, c=(o*12+O)*16+b
// ============================================================================
__global__ void compute_Wt_kernel(const float* __restrict__ W1) {
    int IO = blockIdx.x;
    int I = IO / 12, O = IO % 12;
    int t = threadIdx.x;
    int o = t >> 4, b = t & 15;

    __shared__ float sW1[32][128];
    __shared__ float sT[32][128];

    float acc[64];
#pragma unroll
    for (int i = 0; i < 64; i++) acc[i] = 0.f;

    for (int s0 = 0; s0 < NS; s0 += 32) {
        int ns = min(32, NS - s0);
        for (int j = t; j < ns * 128; j += 256) {
            int ss = j >> 7, io = j & 127;
            sW1[ss][io] = W1[io * NS + s0 + ss];
        }
        for (int j = t; j < ns * 128; j += 256) {
            int ss = j >> 7, ab = j & 127;
            sT[ss][ab] = g_T[((size_t)(s0 + ss) * 144 + IO) * 128 + ab];
        }
        __syncthreads();
        for (int ss = 0; ss < ns; ss++) {
            float w1v[8], tv[8];
#pragma unroll
            for (int i = 0; i < 8; i++) w1v[i] = sW1[ss][i * 16 + o];
#pragma unroll
            for (int a = 0; a < 8; a++) tv[a] = sT[ss][a * 16 + b];
#pragma unroll
            for (int i = 0; i < 8; i++)
#pragma unroll
                for (int a = 0; a < 8; a++)
                    acc[i * 8 + a] += w1v[i] * tv[a];
        }
        __syncthreads();
    }

    int c = (o * 12 + O) * 16 + b;
#pragma unroll
    for (int i = 0; i < 8; i++)
#pragma unroll
        for (int a = 0; a < 8; a++) {
            int r = (i * 12 + I) * 8 + a;
            g_Wt[(size_t)c * K_IN + r] = acc[i * 8 + a];
        }
}

// ============================================================================
// Kernel 3: x -> hi/lo bf16, row-major [M][K]
// ============================================================================
__global__ void convert_x_kernel(const float* __restrict__ x) {
    size_t gt = (size_t)blockIdx.x * blockDim.x + threadIdx.x;
    const float* xp = x + gt * 8;
    float4 v0 = *reinterpret_cast<const float4*>(xp);
    float4 v1 = *reinterpret_cast<const float4*>(xp + 4);
    float f[8] = {v0.x, v0.y, v0.z, v0.w, v1.x, v1.y, v1.z, v1.w};
    uint32_t hw[4], lw[4];
#pragma unroll
    for (int j = 0; j < 4; j++) {
        __nv_bfloat16 h0 = __float2bfloat16(f[2*j]);
        __nv_bfloat16 h1 = __float2bfloat16(f[2*j+1]);
        __nv_bfloat16 l0 = __float2bfloat16(f[2*j]   - __bfloat162float(h0));
        __nv_bfloat16 l1 = __float2bfloat16(f[2*j+1] - __bfloat162float(h1));
        hw[j] = (uint32_t)__bfloat16_as_ushort(h0) | ((uint32_t)__bfloat16_as_ushort(h1) << 16);
        lw[j] = (uint32_t)__bfloat16_as_ushort(l0) | ((uint32_t)__bfloat16_as_ushort(l1) << 16);
    }
    *reinterpret_cast<uint4*>(&g_Ahi[gt * 8]) = make_uint4(hw[0], hw[1], hw[2], hw[3]);
    *reinterpret_cast<uint4*>(&g_Alo[gt * 8]) = make_uint4(lw[0], lw[1], lw[2], lw[3]);
}

// ============================================================================
// Kernel 4: g_Wt (fp32 [n][k]) -> hi/lo bf16 [n][k]
// ============================================================================
__global__ void convert_W_kernel() {
    size_t gt = (size_t)blockIdx.x * blockDim.x + threadIdx.x;
    const float* wp = g_Wt + gt * 8;
    float4 v0 = *reinterpret_cast<const float4*>(wp);
    float4 v1 = *reinterpret_cast<const float4*>(wp + 4);
    float f[8] = {v0.x, v0.y, v0.z, v0.w, v1.x, v1.y, v1.z, v1.w};
    uint32_t hw[4], lw[4];
#pragma unroll
    for (int j = 0; j < 4; j++) {
        __nv_bfloat16 h0 = __float2bfloat16(f[2*j]);
        __nv_bfloat16 h1 = __float2bfloat16(f[2*j+1]);
        __nv_bfloat16 l0 = __float2bfloat16(f[2*j]   - __bfloat162float(h0));
        __nv_bfloat16 l1 = __float2bfloat16(f[2*j+1] - __bfloat162float(h1));
        hw[j] = (uint32_t)__bfloat16_as_ushort(h0) | ((uint32_t)__bfloat16_as_ushort(h1) << 16);
        lw[j] = (uint32_t)__bfloat16_as_ushort(l0) | ((uint32_t)__bfloat16_as_ushort(l1) << 16);
    }
    *reinterpret_cast<uint4*>(&g_Bhi[gt * 8]) = make_uint4(hw[0], hw[1], hw[2], hw[3]);
    *reinterpret_cast<uint4*>(&g_Blo[gt * 8]) = make_uint4(lw[0], lw[1], lw[2], lw[3]);
}

// ============================================================================
// Kernel 5: GEMM via mma.sync bf16.  C = sum over 3 segments + bias.
// 512 threads = 16 warps (4m x 4n), warp tile 32x64, BK=64, 3-stage cp.async,
// ONE __syncthreads per iteration (loads issued post-barrier; wait_group 1).
// ============================================================================
__global__ __launch_bounds__(512, 1)
void gemm_mma_kernel(const float* __restrict__ bias, float* __restrict__ C) {
    extern __shared__ unsigned char smem[];
    const uint32_t sbase = smem_u32(smem);

    const int tid  = threadIdx.x;
    const int wid  = tid >> 5;
    const int lane = tid & 31;
    const int m0 = blockIdx.y * BM;
    const int n0 = blockIdx.x * BN;
    const int warp_m = (wid & 3) * 32;   // 0,32,64,96
    const int warp_n = (wid >> 2) * 64;  // 0,64,128,192

    float acc[2][8][4];
#pragma unroll
    for (int i = 0; i < 2; i++)
#pragma unroll
        for (int j = 0; j < 8; j++)
#pragma unroll
            for (int q = 0; q < 4; q++) acc[i][j][q] = 0.f;

    // ---- stage loader: A 1024 chunks (2/thread), B 2048 chunks (4/thread) ----
    auto load_stage = [&](int stage, int it) {
        int seg = it / NKB;
        int k0  = (it - seg * NKB) * BK;
        const __nv_bfloat16* Aseg = (seg == 1) ? g_Alo : g_Ahi;
        const __nv_bfloat16* Bseg = (seg == 2) ? g_Blo : g_Bhi;
        uint32_t sA = sbase + stage * STAGE_BYTES;
        uint32_t sB = sA + A_STAGE_BYTES;
#pragma unroll
        for (int j = 0; j < 2; j++) {
            int id  = tid + j * 512;
            int row = id >> 3;
            int c   = id & 7;
            cp16(sA + swz128(row, c), Aseg + (size_t)(m0 + row) * K_IN + k0 + c * 8);
        }
#pragma unroll
        for (int j = 0; j < 4; j++) {
            int id  = tid + j * 512;
            int row = id >> 3;
            int c   = id & 7;
            cp16(sB + swz128(row, c), Bseg + (size_t)(n0 + row) * K_IN + k0 + c * 8);
        }
    };

    // Prologue: stages 0 and 1 (groups g0, g1)
    load_stage(0, 0); CP_COMMIT();
    load_stage(1, 1); CP_COMMIT();

    for (int it = 0; it < NIT; it++) {
        CP_WAIT1();               // group for stage it%3 complete (g_{it+1} may fly)
        __syncthreads();          // all warps done with stage (it+2)%3's old data
        if (it + 2 < NIT) load_stage((it + 2) % NSTAGES, it + 2);
        CP_COMMIT();

        uint32_t sA = sbase + (it % NSTAGES) * STAGE_BYTES;
        uint32_t sB = sA + A_STAGE_BYTES;

#pragma unroll
        for (int ks = 0; ks < 4; ks++) {
            uint32_t aF[2][4];
#pragma unroll
            for (int mt = 0; mt < 2; mt++) {
                int r = warp_m + mt * 16 + (lane & 15);
                int c = ks * 2 + (lane >> 4);
                LDMATRIX_X4(aF[mt][0], aF[mt][1], aF[mt][2], aF[mt][3], sA + swz128(r, c));
            }
            uint32_t bF[4][4];
#pragma unroll
            for (int nt = 0; nt < 4; nt++) {
                int r = warp_n + nt * 16 + (lane & 15);
                int c = ks * 2 + (lane >> 4);
                LDMATRIX_X4(bF[nt][0], bF[nt][1], bF[nt][2], bF[nt][3], sB + swz128(r, c));
            }
#pragma unroll
            for (int mt = 0; mt < 2; mt++)
#pragma unroll
                for (int nt = 0; nt < 4; nt++)
#pragma unroll
                    for (int p = 0; p < 2; p++) {
                        MMA_BF16(acc[mt][nt * 2 + p],
                                 aF[mt][0], aF[mt][1], aF[mt][2], aF[mt][3],
                                 bF[nt][p], bF[nt][2 + p]);
                    }
        }
    }

    // ---- Epilogue: bias + store ----
    const int g = lane >> 2, tig = lane & 3;
    float bv[8][2];
#pragma unroll
    for (int nn = 0; nn < 8; nn++) {
        int col = n0 + warp_n + nn * 8 + tig * 2;
        bv[nn][0] = __ldg(&bias[col]);
        bv[nn][1] = __ldg(&bias[col + 1]);
    }
#pragma unroll
    for (int mt = 0; mt < 2; mt++) {
        int r0 = m0 + warp_m + mt * 16 + g;
        int r1 = r0 + 8;
#pragma unroll
        for (int nn = 0; nn < 8; nn++) {
            int col = n0 + warp_n + nn * 8 + tig * 2;
            float2 v0 = make_float2(acc[mt][nn][0] + bv[nn][0], acc[mt][nn][1] + bv[nn][1]);
            float2 v1 = make_float2(acc[mt][nn][2] + bv[nn][0], acc[mt][nn][3] + bv[nn][1]);
            *reinterpret_cast<float2*>(&C[(size_t)r0 * N_OUT + col]) = v0;
            *reinterpret_cast<float2*>(&C[(size_t)r1 * N_OUT + col]) = v1;
        }
    }
}

// ============================================================================
// Launch. Inputs: x, W_1, W_2, W_3, b. Output fp32 (32768, 3072).
// ============================================================================
extern "C" void kernel_launch(void* const* d_in, const int* in_sizes, int n_in,
                              void* d_out, int out_size) {
    const float* x  = (const float*)d_in[0];
    const float* W1 = (const float*)d_in[1];
    const float* W2 = (const float*)d_in[2];
    const float* W3 = (const float*)d_in[3];
    const float* b  = (const float*)d_in[4];
    float* out = (float*)d_out;

    cudaFuncSetAttribute(gemm_mma_kernel,
                         cudaFuncAttributeMaxDynamicSharedMemorySize, SMEM_TOTAL);
    cudaFuncSetAttribute(compute_T_kernel,
                         cudaFuncAttributeMaxDynamicSharedMemorySize, NS * 128 * 4);

    compute_T_kernel<<<((NS + 7) / 8) * 144, 128, NS * 128 * 4>>>(W2, W3);
    compute_Wt_kernel<<<144, 256>>>(W1);
    convert_x_kernel<<<(M_TOK * 96) / 256, 256>>>(x);
    convert_W_kernel<<<(N_OUT * 96) / 256, 256>>>();
    gemm_mma_kernel<<<dim3(N_TILES, M_TILES), 512, SMEM_TOTAL>>>(b, out);
}

// round 10
// speedup vs baseline: 2.0104x; 1.0133x over previous
#include <cuda_runtime.h>
#include <cuda_bf16.h>
#include <cstdint>

// ============================================================================
// Problem constants
// ============================================================================
#define M_TOK 32768
#define K_IN  768
#define N_OUT 3072
#define NS    134
#define T_BLOCKS (NS * 144)

// GEMM tiling
#define BM 128
#define BN 256
#define BK 64
#define NKB (K_IN / BK)        // 12 k-blocks per segment
#define NSEG 3                 // hi*hi, lo*hi, hi*lo
#define NIT (NSEG * NKB)       // 36
#define M_TILES (M_TOK / BM)   // 256
#define N_TILES (N_OUT / BN)   // 12

#define A_STAGE_BYTES (BM * BK * 2)      // 16384
#define B_STAGE_BYTES (BN * BK * 2)      // 32768
#define STAGE_BYTES (A_STAGE_BYTES + B_STAGE_BYTES)  // 49152
#define NSTAGES 3
#define SMEM_TOTAL (NSTAGES * STAGE_BYTES)           // 147456

// ============================================================================
// Device scratch (allocation-free)
// ============================================================================
__device__ float g_T[(size_t)T_BLOCKS * 128];          // 9.9 MB
__device__ float g_Wt[(size_t)N_OUT * K_IN];           // 9.4 MB, W transposed [n][k]
__device__ __nv_bfloat16 g_Ahi[(size_t)M_TOK * K_IN];  // 48 MB
__device__ __nv_bfloat16 g_Alo[(size_t)M_TOK * K_IN];  // 48 MB
__device__ __nv_bfloat16 g_Bhi[(size_t)N_OUT * K_IN];  // 4.5 MB
__device__ __nv_bfloat16 g_Blo[(size_t)N_OUT * K_IN];  // 4.5 MB

// ============================================================================
// PTX helpers (plain sm_80+ PTX only)
// ============================================================================
__device__ __forceinline__ uint32_t smem_u32(const void* p) {
    uint32_t a;
    asm("{ .reg .u64 t; cvta.to.shared.u64 t, %1; cvt.u32.u64 %0, t; }" : "=r"(a) : "l"(p));
    return a;
}

__device__ __forceinline__ void cp16(uint32_t dst, const void* src) {
    asm volatile("cp.async.cg.shared.global [%0], [%1], 16;" :: "r"(dst), "l"(src));
}
#define CP_COMMIT() asm volatile("cp.async.commit_group;" ::: "memory")
#define CP_WAIT1()  asm volatile("cp.async.wait_group 1;" ::: "memory")

#define LDMATRIX_X4(r0, r1, r2, r3, addr) \
    asm volatile("ldmatrix.sync.aligned.m8n8.x4.shared.b16 {%0,%1,%2,%3}, [%4];" \
                 : "=r"(r0), "=r"(r1), "=r"(r2), "=r"(r3) : "r"(addr))

#define MMA_BF16(d, a0, a1, a2, a3, b0, b1) \
    asm volatile("mma.sync.aligned.m16n8k16.row.col.f32.bf16.bf16.f32 " \
                 "{%0,%1,%2,%3}, {%4,%5,%6,%7}, {%8,%9}, {%0,%1,%2,%3};" \
                 : "+f"((d)[0]), "+f"((d)[1]), "+f"((d)[2]), "+f"((d)[3]) \
                 : "r"(a0), "r"(a1), "r"(a2), "r"(a3), "r"(b0), "r"(b1))

// 128B-row swizzle: row r, 16B chunk c (0..7) -> c ^ (r & 7).
__device__ __forceinline__ uint32_t swz128(int r, int c) {
    return (uint32_t)(r * 128 + ((c ^ (r & 7)) << 4));
}

// ============================================================================
// Kernel 1: T[s,I,O,a,b] = sum_S W2[s,I,O,S] * W3[S,a,b]
// W3 (68.6 KB) cached in dynamic smem; 8 s-values per block.
// ============================================================================
__global__ void compute_T_kernel(const float* __restrict__ W2,
                                 const float* __restrict__ W3) {
    extern __shared__ float sW3[];           // NS*128 floats
    __shared__ float sw2[8][NS];
    int blk = blockIdx.x;
    int sc  = blk / 144;
    int IO  = blk % 144;
    int t   = threadIdx.x;

    for (int j = t; j < NS * 128; j += 128) sW3[j] = W3[j];
    int s0  = sc * 8;
    int nsv = min(8, NS - s0);
    for (int j = t; j < nsv * NS; j += 128) {
        int ss = j / NS, k = j - ss * NS;
        sw2[ss][k] = W2[((size_t)(s0 + ss) * 144 + IO) * NS + k];
    }
    __syncthreads();

    for (int ss = 0; ss < nsv; ss++) {
        float acc = 0.f;
#pragma unroll 2
        for (int S = 0; S < NS; S++)
            acc += sw2[ss][S] * sW3[S * 128 + t];
        g_T[((size_t)(s0 + ss) * 144 + IO) * 128 + t] = acc;
    }
}

// ============================================================================
// Kernel 2: W transposed — g_Wt[c*768 + r] = sum_s W1[i,o,s] * T[s,I,O,a,b]
// ============================================================================
__global__ void compute_Wt_kernel(const float* __restrict__ W1) {
    int IO = blockIdx.x;
    int I = IO / 12, O = IO % 12;
    int t = threadIdx.x;
    int o = t >> 4, b = t & 15;

    __shared__ float sW1[32][128];
    __shared__ float sT[32][128];

    float acc[64];
#pragma unroll
    for (int i = 0; i < 64; i++) acc[i] = 0.f;

    for (int s0 = 0; s0 < NS; s0 += 32) {
        int ns = min(32, NS - s0);
        for (int j = t; j < ns * 128; j += 256) {
            int ss = j >> 7, io = j & 127;
            sW1[ss][io] = W1[io * NS + s0 + ss];
        }
        for (int j = t; j < ns * 128; j += 256) {
            int ss = j >> 7, ab = j & 127;
            sT[ss][ab] = g_T[((size_t)(s0 + ss) * 144 + IO) * 128 + ab];
        }
        __syncthreads();
        for (int ss = 0; ss < ns; ss++) {
            float w1v[8], tv[8];
#pragma unroll
            for (int i = 0; i < 8; i++) w1v[i] = sW1[ss][i * 16 + o];
#pragma unroll
            for (int a = 0; a < 8; a++) tv[a] = sT[ss][a * 16 + b];
#pragma unroll
            for (int i = 0; i < 8; i++)
#pragma unroll
                for (int a = 0; a < 8; a++)
                    acc[i * 8 + a] += w1v[i] * tv[a];
        }
        __syncthreads();
    }

    int c = (o * 12 + O) * 16 + b;
#pragma unroll
    for (int i = 0; i < 8; i++)
#pragma unroll
        for (int a = 0; a < 8; a++) {
            int r = (i * 12 + I) * 8 + a;
            g_Wt[(size_t)c * K_IN + r] = acc[i * 8 + a];
        }
}

// ============================================================================
// Kernel 3: x -> hi/lo bf16, row-major [M][K]
// ============================================================================
__global__ void convert_x_kernel(const float* __restrict__ x) {
    size_t gt = (size_t)blockIdx.x * blockDim.x + threadIdx.x;
    const float* xp = x + gt * 8;
    float4 v0 = *reinterpret_cast<const float4*>(xp);
    float4 v1 = *reinterpret_cast<const float4*>(xp + 4);
    float f[8] = {v0.x, v0.y, v0.z, v0.w, v1.x, v1.y, v1.z, v1.w};
    uint32_t hw[4], lw[4];
#pragma unroll
    for (int j = 0; j < 4; j++) {
        __nv_bfloat16 h0 = __float2bfloat16(f[2*j]);
        __nv_bfloat16 h1 = __float2bfloat16(f[2*j+1]);
        __nv_bfloat16 l0 = __float2bfloat16(f[2*j]   - __bfloat162float(h0));
        __nv_bfloat16 l1 = __float2bfloat16(f[2*j+1] - __bfloat162float(h1));
        hw[j] = (uint32_t)__bfloat16_as_ushort(h0) | ((uint32_t)__bfloat16_as_ushort(h1) << 16);
        lw[j] = (uint32_t)__bfloat16_as_ushort(l0) | ((uint32_t)__bfloat16_as_ushort(l1) << 16);
    }
    *reinterpret_cast<uint4*>(&g_Ahi[gt * 8]) = make_uint4(hw[0], hw[1], hw[2], hw[3]);
    *reinterpret_cast<uint4*>(&g_Alo[gt * 8]) = make_uint4(lw[0], lw[1], lw[2], lw[3]);
}

// ============================================================================
// Kernel 4: g_Wt (fp32 [n][k]) -> hi/lo bf16 [n][k]
// ============================================================================
__global__ void convert_W_kernel() {
    size_t gt = (size_t)blockIdx.x * blockDim.x + threadIdx.x;
    const float* wp = g_Wt + gt * 8;
    float4 v0 = *reinterpret_cast<const float4*>(wp);
    float4 v1 = *reinterpret_cast<const float4*>(wp + 4);
    float f[8] = {v0.x, v0.y, v0.z, v0.w, v1.x, v1.y, v1.z, v1.w};
    uint32_t hw[4], lw[4];
#pragma unroll
    for (int j = 0; j < 4; j++) {
        __nv_bfloat16 h0 = __float2bfloat16(f[2*j]);
        __nv_bfloat16 h1 = __float2bfloat16(f[2*j+1]);
        __nv_bfloat16 l0 = __float2bfloat16(f[2*j]   - __bfloat162float(h0));
        __nv_bfloat16 l1 = __float2bfloat16(f[2*j+1] - __bfloat162float(h1));
        hw[j] = (uint32_t)__bfloat16_as_ushort(h0) | ((uint32_t)__bfloat16_as_ushort(h1) << 16);
        lw[j] = (uint32_t)__bfloat16_as_ushort(l0) | ((uint32_t)__bfloat16_as_ushort(l1) << 16);
    }
    *reinterpret_cast<uint4*>(&g_Bhi[gt * 8]) = make_uint4(hw[0], hw[1], hw[2], hw[3]);
    *reinterpret_cast<uint4*>(&g_Blo[gt * 8]) = make_uint4(lw[0], lw[1], lw[2], lw[3]);
}

// ============================================================================
// Kernel 5: GEMM via mma.sync bf16.  256 threads = 8 warps (2m x 4n),
// warp tile 64x64, BK=64, 3-stage cp.async, double-buffered fragments.
// ============================================================================
__global__ __launch_bounds__(256, 1)
void gemm_mma_kernel(const float* __restrict__ bias, float* __restrict__ C) {
    extern __shared__ unsigned char smem[];
    const uint32_t sbase = smem_u32(smem);

    const int tid  = threadIdx.x;
    const int wid  = tid >> 5;
    const int lane = tid & 31;
    const int m0 = blockIdx.y * BM;
    const int n0 = blockIdx.x * BN;
    const int warp_m = (wid & 1) * 64;   // 0,64
    const int warp_n = (wid >> 1) * 64;  // 0,64,128,192

    float acc[4][8][4];
#pragma unroll
    for (int i = 0; i < 4; i++)
#pragma unroll
        for (int j = 0; j < 8; j++)
#pragma unroll
            for (int q = 0; q < 4; q++) acc[i][j][q] = 0.f;

    // ---- stage loader: A 1024 chunks (4/thread), B 2048 chunks (8/thread) ----
    auto load_stage = [&](int stage, int it) {
        int seg = it / NKB;
        int k0  = (it - seg * NKB) * BK;
        const __nv_bfloat16* Aseg = (seg == 1) ? g_Alo : g_Ahi;
        const __nv_bfloat16* Bseg = (seg == 2) ? g_Blo : g_Bhi;
        uint32_t sA = sbase + stage * STAGE_BYTES;
        uint32_t sB = sA + A_STAGE_BYTES;
#pragma unroll
        for (int j = 0; j < 4; j++) {
            int id  = tid + j * 256;
            int row = id >> 3;
            int c   = id & 7;
            cp16(sA + swz128(row, c), Aseg + (size_t)(m0 + row) * K_IN + k0 + c * 8);
        }
#pragma unroll
        for (int j = 0; j < 8; j++) {
            int id  = tid + j * 256;
            int row = id >> 3;
            int c   = id & 7;
            cp16(sB + swz128(row, c), Bseg + (size_t)(n0 + row) * K_IN + k0 + c * 8);
        }
    };

    // Fragment double buffers
    uint32_t aF[2][4][4], bF[2][4][4];
    const int fr = lane & 15;
    const int fc = lane >> 4;

    auto load_frags = [&](uint32_t sA, uint32_t sB, int ks, int buf) {
#pragma unroll
        for (int mt = 0; mt < 4; mt++) {
            int r = warp_m + mt * 16 + fr;
            LDMATRIX_X4(aF[buf][mt][0], aF[buf][mt][1], aF[buf][mt][2], aF[buf][mt][3],
                        sA + swz128(r, ks * 2 + fc));
        }
#pragma unroll
        for (int nt = 0; nt < 4; nt++) {
            int r = warp_n + nt * 16 + fr;
            LDMATRIX_X4(bF[buf][nt][0], bF[buf][nt][1], bF[buf][nt][2], bF[buf][nt][3],
                        sB + swz128(r, ks * 2 + fc));
        }
    };

    auto do_mma = [&](int buf) {
#pragma unroll
        for (int mt = 0; mt < 4; mt++)
#pragma unroll
            for (int nt = 0; nt < 4; nt++)
#pragma unroll
                for (int p = 0; p < 2; p++) {
                    MMA_BF16(acc[mt][nt * 2 + p],
                             aF[buf][mt][0], aF[buf][mt][1], aF[buf][mt][2], aF[buf][mt][3],
                             bF[buf][nt][p], bF[buf][nt][2 + p]);
                }
    };

    // Prologue: stages 0 and 1
    load_stage(0, 0); CP_COMMIT();
    load_stage(1, 1); CP_COMMIT();

    for (int it = 0; it < NIT; it++) {
        CP_WAIT1();               // stage it%3 resident (next group may still fly)
        __syncthreads();          // all warps done reading stage (it+2)%3's old data
        if (it + 2 < NIT) load_stage((it + 2) % NSTAGES, it + 2);
        CP_COMMIT();

        uint32_t sA = sbase + (it % NSTAGES) * STAGE_BYTES;
        uint32_t sB = sA + A_STAGE_BYTES;

        load_frags(sA, sB, 0, 0);
#pragma unroll
        for (int ks = 0; ks < 4; ks++) {
            if (ks < 3) load_frags(sA, sB, ks + 1, (ks + 1) & 1);
            do_mma(ks & 1);
        }
    }

    // ---- Epilogue: bias + store ----
    const int g = lane >> 2, tig = lane & 3;
    float bv[8][2];
#pragma unroll
    for (int nn = 0; nn < 8; nn++) {
        int col = n0 + warp_n + nn * 8 + tig * 2;
        bv[nn][0] = __ldg(&bias[col]);
        bv[nn][1] = __ldg(&bias[col + 1]);
    }
#pragma unroll
    for (int mt = 0; mt < 4; mt++) {
        int r0 = m0 + warp_m + mt * 16 + g;
        int r1 = r0 + 8;
#pragma unroll
        for (int nn = 0; nn < 8; nn++) {
            int col = n0 + warp_n + nn * 8 + tig * 2;
            float2 v0 = make_float2(acc[mt][nn][0] + bv[nn][0], acc[mt][nn][1] + bv[nn][1]);
            float2 v1 = make_float2(acc[mt][nn][2] + bv[nn][0], acc[mt][nn][3] + bv[nn][1]);
            *reinterpret_cast<float2*>(&C[(size_t)r0 * N_OUT + col]) = v0;
            *reinterpret_cast<float2*>(&C[(size_t)r1 * N_OUT + col]) = v1;
        }
    }
}

// ============================================================================
// Launch. Inputs: x, W_1, W_2, W_3, b. Output fp32 (32768, 3072).
// ============================================================================
extern "C" void kernel_launch(void* const* d_in, const int* in_sizes, int n_in,
                              void* d_out, int out_size) {
    const float* x  = (const float*)d_in[0];
    const float* W1 = (const float*)d_in[1];
    const float* W2 = (const float*)d_in[2];
    const float* W3 = (const float*)d_in[3];
    const float* b  = (const float*)d_in[4];
    float* out = (float*)d_out;

    cudaFuncSetAttribute(gemm_mma_kernel,
                         cudaFuncAttributeMaxDynamicSharedMemorySize, SMEM_TOTAL);
    cudaFuncSetAttribute(compute_T_kernel,
                         cudaFuncAttributeMaxDynamicSharedMemorySize, NS * 128 * 4);

    compute_T_kernel<<<((NS + 7) / 8) * 144, 128, NS * 128 * 4>>>(W2, W3);
    compute_Wt_kernel<<<144, 256>>>(W1);
    convert_x_kernel<<<(M_TOK * 96) / 256, 256>>>(x);
    convert_W_kernel<<<(N_OUT * 96) / 256, 256>>>();
    gemm_mma_kernel<<<dim3(N_TILES, M_TILES), 256, SMEM_TOTAL>>>(b, out);
}